// round 2
// baseline (speedup 1.0000x reference)
#include <cuda_runtime.h>
#include <cuda_bf16.h>
#include <cstdint>

// Problem constants (shape-specialized; guarded at launch with runtime sizes)
#define MAX_NODES 100000
#define F_IN      128
#define F_OUT     64

// 25.6 MB scratch for xw = x @ W (allocation-free rule: __device__ global)
__device__ __align__(16) float g_xw[(size_t)MAX_NODES * F_OUT];

// ---------------------------------------------------------------------------
// Kernel 1: out[r][:] = b[:]   (broadcast bias init; out poisoned by harness)
// ---------------------------------------------------------------------------
__global__ void init_bias_kernel(float* __restrict__ out,
                                 const float* __restrict__ b,
                                 int n_rows) {
    __shared__ float4 bs[F_OUT / 4];
    if (threadIdx.x < F_OUT / 4) {
        bs[threadIdx.x] = ((const float4*)b)[threadIdx.x];
    }
    __syncthreads();
    int total = n_rows * (F_OUT / 4);  // float4 elements
    for (int i = blockIdx.x * blockDim.x + threadIdx.x; i < total;
         i += gridDim.x * blockDim.x) {
        ((float4*)out)[i] = bs[i & (F_OUT / 4 - 1)];
    }
}

// ---------------------------------------------------------------------------
// Kernel 2: dense GEMM  xw[M,64] = x[M,128] @ W[128,64]
// BM=32 rows per block, full K=128 and full W in shared (48 KB total).
// 256 threads, each computes a 2x4 register tile.
// ---------------------------------------------------------------------------
#define BM 32

__global__ __launch_bounds__(256) void gemm_kernel(
    const float* __restrict__ x,
    const float* __restrict__ W,
    int n_nodes) {
    __shared__ float xsT[F_IN][BM];      // transposed x tile: [k][row]  16 KB
    __shared__ float Ws[F_IN][F_OUT];    // [k][f]                       32 KB

    const int t = threadIdx.x;           // 0..255
    const int row0 = blockIdx.x * BM;

    // Load W (8192 floats = 2048 float4), fully coalesced
    {
        const float4* W4 = (const float4*)W;
        float4* Ws4 = (float4*)Ws;
#pragma unroll
        for (int i = 0; i < 8; i++) Ws4[t + i * 256] = W4[t + i * 256];
    }

    // Load x tile transposed into smem.
    // thread: row = t&31, kc0 = t>>5 (0..7); 4 iterations cover kc 0..31.
    {
        const int row = t & 31;
        const int kc0 = t >> 5;
        const int grow = row0 + row;
        const bool ok = (grow < n_nodes);
        const float4* xrow4 =
            (const float4*)(x + (size_t)(ok ? grow : 0) * F_IN);
#pragma unroll
        for (int i = 0; i < 4; i++) {
            int kc = kc0 + i * 8;  // float4 index within the row
            float4 v = ok ? xrow4[kc] : make_float4(0.f, 0.f, 0.f, 0.f);
            xsT[kc * 4 + 0][row] = v.x;
            xsT[kc * 4 + 1][row] = v.y;
            xsT[kc * 4 + 2][row] = v.z;
            xsT[kc * 4 + 3][row] = v.w;
        }
    }
    __syncthreads();

    // Compute: thread (tx,ty) -> rows ty*2..+1, cols tx*4..+3
    const int tx = t & 15;   // col group
    const int ty = t >> 4;   // row group (0..15)

    float acc[2][4];
#pragma unroll
    for (int i = 0; i < 2; i++)
#pragma unroll
        for (int j = 0; j < 4; j++) acc[i][j] = 0.f;

#pragma unroll 16
    for (int k = 0; k < F_IN; k++) {
        float2 xv = ((const float2*)(&xsT[k][0]))[ty];
        float4 wv = ((const float4*)(&Ws[k][0]))[tx];
        acc[0][0] += xv.x * wv.x;
        acc[0][1] += xv.x * wv.y;
        acc[0][2] += xv.x * wv.z;
        acc[0][3] += xv.x * wv.w;
        acc[1][0] += xv.y * wv.x;
        acc[1][1] += xv.y * wv.y;
        acc[1][2] += xv.y * wv.z;
        acc[1][3] += xv.y * wv.w;
    }

#pragma unroll
    for (int i = 0; i < 2; i++) {
        int grow = row0 + ty * 2 + i;
        if (grow < n_nodes) {
            float4 v = make_float4(acc[i][0], acc[i][1], acc[i][2], acc[i][3]);
            ((float4*)(g_xw + (size_t)grow * F_OUT))[tx] = v;
        }
    }
}

// ---------------------------------------------------------------------------
// Kernel 3: SpMM scatter. 16 threads per edge; each handles one float4 chunk.
// Gather xw[col] (L2-resident, 25.6 MB), scale, red.global.add.v4.f32 to out.
// NOTE: indices are int32 (JAX x64 disabled downcasts the requested int64).
// ---------------------------------------------------------------------------
__global__ __launch_bounds__(256) void spmm_kernel(
    const int* __restrict__ adj_row,
    const int* __restrict__ adj_col,
    const float* __restrict__ adj_val,
    float* __restrict__ out,
    int n_edges, int n_nodes) {
    int gid = blockIdx.x * blockDim.x + threadIdx.x;
    int e = gid >> 4;
    if (e >= n_edges) return;
    int c = gid & 15;  // float4 chunk 0..15

    int r = adj_row[e];
    int col = adj_col[e];
    float v = adj_val[e];

    // Defense-in-depth: skip malformed indices instead of crashing.
    if ((unsigned)r >= (unsigned)n_nodes || (unsigned)col >= (unsigned)n_nodes)
        return;

    float4 m = ((const float4*)g_xw)[(size_t)col * (F_OUT / 4) + c];
    float mx = v * m.x;
    float my = v * m.y;
    float mz = v * m.z;
    float mw = v * m.w;

    float* dst = out + (size_t)r * F_OUT + c * 4;
    asm volatile("red.global.add.v4.f32 [%0], {%1, %2, %3, %4};"
                 :
                 : "l"(dst), "f"(mx), "f"(my), "f"(mz), "f"(mw)
                 : "memory");
}

// ---------------------------------------------------------------------------
// Launch
// ---------------------------------------------------------------------------
extern "C" void kernel_launch(void* const* d_in, const int* in_sizes, int n_in,
                              void* d_out, int out_size) {
    const float* x = (const float*)d_in[0];
    const int* adj_row = (const int*)d_in[1];
    const int* adj_col = (const int*)d_in[2];
    const float* adj_val = (const float*)d_in[3];
    const float* W = (const float*)d_in[4];
    const float* b = (const float*)d_in[5];
    float* out = (float*)d_out;

    const int n_nodes = in_sizes[0] / F_IN;
    const int n_edges = in_sizes[1];

    // 1) out = b (broadcast). Independent of GEMM.
    {
        int total4 = n_nodes * (F_OUT / 4);
        int blocks = (total4 + 255) / 256;
        if (blocks > 2960) blocks = 2960;  // grid-stride, ~20 blocks/SM
        init_bias_kernel<<<blocks, 256>>>(out, b, n_nodes);
    }

    // 2) xw = x @ W into g_xw
    {
        int blocks = (n_nodes + BM - 1) / BM;
        gemm_kernel<<<blocks, 256>>>(x, W, n_nodes);
    }

    // 3) scatter-add messages
    {
        long long total = (long long)n_edges * 16;
        int blocks = (int)((total + 255) / 256);
        spmm_kernel<<<blocks, 256>>>(adj_row, adj_col, adj_val, out, n_edges,
                                     n_nodes);
    }
}

// round 4
// speedup vs baseline: 1.2149x; 1.2149x over previous
#include <cuda_runtime.h>
#include <cuda_bf16.h>
#include <cstdint>

#define MAX_NODES 100000
#define MAX_EDGES 1600000
#define F_IN      128
#define F_OUT     64

// Scratch (allocation-free rule: __device__ globals)
__device__ __align__(16) float g_xw[(size_t)MAX_NODES * F_OUT];   // 25.6 MB
__device__ __align__(16) int2  g_edges[MAX_EDGES];                // {col, val-bits} 12.8 MB
__device__ int g_count[MAX_NODES];
__device__ int g_offset[MAX_NODES + 1];
__device__ int g_pos[MAX_NODES];
__device__ int g_bsum[512];
__device__ int g_boff[512];

#define SCAN_BLK 512

// ---------------------------------------------------------------------------
// CSR build: zero -> histogram -> scan(a,b,c) -> scatter
// ---------------------------------------------------------------------------
__global__ void zero_count_kernel(int n_nodes) {
    int i = blockIdx.x * blockDim.x + threadIdx.x;
    if (i < n_nodes) g_count[i] = 0;
}

__global__ void hist_kernel(const int* __restrict__ adj_row, int n_edges) {
    int e = blockIdx.x * blockDim.x + threadIdx.x;
    if (e < n_edges) {
        int r = adj_row[e];
        if ((unsigned)r < (unsigned)MAX_NODES) atomicAdd(&g_count[r], 1);
    }
}

__global__ __launch_bounds__(SCAN_BLK) void scan_a_kernel(int n_nodes) {
    __shared__ int s[SCAN_BLK];
    int t = threadIdx.x;
    int idx = blockIdx.x * SCAN_BLK + t;
    s[t] = (idx < n_nodes) ? g_count[idx] : 0;
    __syncthreads();
#pragma unroll
    for (int d = SCAN_BLK / 2; d > 0; d >>= 1) {
        if (t < d) s[t] += s[t + d];
        __syncthreads();
    }
    if (t == 0) g_bsum[blockIdx.x] = s[0];
}

__global__ __launch_bounds__(SCAN_BLK) void scan_b_kernel(int nblocks,
                                                          int n_nodes) {
    __shared__ int s[SCAN_BLK];
    int t = threadIdx.x;
    s[t] = (t < nblocks) ? g_bsum[t] : 0;
    __syncthreads();
    // Hillis-Steele inclusive scan
    for (int d = 1; d < SCAN_BLK; d <<= 1) {
        int tmp = (t >= d) ? s[t - d] : 0;
        __syncthreads();
        s[t] += tmp;
        __syncthreads();
    }
    if (t < nblocks) g_boff[t] = (t == 0) ? 0 : s[t - 1];
    if (t == nblocks - 1) g_offset[n_nodes] = s[t];  // total edges
}

__global__ __launch_bounds__(SCAN_BLK) void scan_c_kernel(int n_nodes) {
    __shared__ int s[SCAN_BLK];
    int t = threadIdx.x;
    int idx = blockIdx.x * SCAN_BLK + t;
    int v = (idx < n_nodes) ? g_count[idx] : 0;
    s[t] = v;
    __syncthreads();
    for (int d = 1; d < SCAN_BLK; d <<= 1) {
        int tmp = (t >= d) ? s[t - d] : 0;
        __syncthreads();
        s[t] += tmp;
        __syncthreads();
    }
    if (idx < n_nodes) {
        int off = g_boff[blockIdx.x] + s[t] - v;  // exclusive
        g_offset[idx] = off;
        g_pos[idx] = off;
    }
}

__global__ void scatter_kernel(const int* __restrict__ adj_row,
                               const int* __restrict__ adj_col,
                               const float* __restrict__ adj_val,
                               int n_edges) {
    int e = blockIdx.x * blockDim.x + threadIdx.x;
    if (e >= n_edges) return;
    int r = adj_row[e];
    if ((unsigned)r >= (unsigned)MAX_NODES) return;
    int pos = atomicAdd(&g_pos[r], 1);
    if ((unsigned)pos < (unsigned)MAX_EDGES)
        g_edges[pos] = make_int2(adj_col[e], __float_as_int(adj_val[e]));
}

// ---------------------------------------------------------------------------
// Dense GEMM  xw[M,64] = x[M,128] @ W[128,64]  (BM=32, 2x4 register tile)
// ---------------------------------------------------------------------------
#define BM 32

__global__ __launch_bounds__(256) void gemm_kernel(
    const float* __restrict__ x,
    const float* __restrict__ W,
    int n_nodes) {
    __shared__ float xsT[F_IN][BM];      // [k][row]  16 KB
    __shared__ float Ws[F_IN][F_OUT];    // [k][f]    32 KB

    const int t = threadIdx.x;
    const int row0 = blockIdx.x * BM;

    {
        const float4* W4 = (const float4*)W;
        float4* Ws4 = (float4*)Ws;
#pragma unroll
        for (int i = 0; i < 8; i++) Ws4[t + i * 256] = W4[t + i * 256];
    }
    {
        const int row = t & 31;
        const int kc0 = t >> 5;
        const int grow = row0 + row;
        const bool ok = (grow < n_nodes);
        const float4* xrow4 =
            (const float4*)(x + (size_t)(ok ? grow : 0) * F_IN);
#pragma unroll
        for (int i = 0; i < 4; i++) {
            int kc = kc0 + i * 8;
            float4 v = ok ? xrow4[kc] : make_float4(0.f, 0.f, 0.f, 0.f);
            xsT[kc * 4 + 0][row] = v.x;
            xsT[kc * 4 + 1][row] = v.y;
            xsT[kc * 4 + 2][row] = v.z;
            xsT[kc * 4 + 3][row] = v.w;
        }
    }
    __syncthreads();

    const int tx = t & 15;
    const int ty = t >> 4;

    float acc[2][4];
#pragma unroll
    for (int i = 0; i < 2; i++)
#pragma unroll
        for (int j = 0; j < 4; j++) acc[i][j] = 0.f;

#pragma unroll 16
    for (int k = 0; k < F_IN; k++) {
        float2 xv = ((const float2*)(&xsT[k][0]))[ty];
        float4 wv = ((const float4*)(&Ws[k][0]))[tx];
        acc[0][0] += xv.x * wv.x;
        acc[0][1] += xv.x * wv.y;
        acc[0][2] += xv.x * wv.z;
        acc[0][3] += xv.x * wv.w;
        acc[1][0] += xv.y * wv.x;
        acc[1][1] += xv.y * wv.y;
        acc[1][2] += xv.y * wv.z;
        acc[1][3] += xv.y * wv.w;
    }

#pragma unroll
    for (int i = 0; i < 2; i++) {
        int grow = row0 + ty * 2 + i;
        if (grow < n_nodes) {
            float4 v = make_float4(acc[i][0], acc[i][1], acc[i][2], acc[i][3]);
            ((float4*)(g_xw + (size_t)grow * F_OUT))[tx] = v;
        }
    }
}

// ---------------------------------------------------------------------------
// CSR aggregation: 16 threads per row, register accumulation, no atomics.
// out[r] = b + sum over row's edges of val * xw[col]
// ---------------------------------------------------------------------------
__global__ __launch_bounds__(256) void agg_kernel(
    const float* __restrict__ b,
    float* __restrict__ out,
    int n_nodes) {
    int gid = blockIdx.x * blockDim.x + threadIdx.x;
    int r = gid >> 4;
    if (r >= n_nodes) return;
    int c = gid & 15;  // float4 chunk

    int s = g_offset[r];
    int e = g_offset[r + 1];

    float4 acc = ((const float4*)b)[c];
    const float4* xw4 = (const float4*)g_xw;

    int i = s;
    // 2-deep software pipeline for the dependent gather
    for (; i + 1 < e; i += 2) {
        int2 e0 = g_edges[i];
        int2 e1 = g_edges[i + 1];
        float4 m0 = xw4[(size_t)e0.x * 16 + c];
        float4 m1 = xw4[(size_t)e1.x * 16 + c];
        float v0 = __int_as_float(e0.y);
        float v1 = __int_as_float(e1.y);
        acc.x += v0 * m0.x + v1 * m1.x;
        acc.y += v0 * m0.y + v1 * m1.y;
        acc.z += v0 * m0.z + v1 * m1.z;
        acc.w += v0 * m0.w + v1 * m1.w;
    }
    if (i < e) {
        int2 e0 = g_edges[i];
        float4 m0 = xw4[(size_t)e0.x * 16 + c];
        float v0 = __int_as_float(e0.y);
        acc.x += v0 * m0.x;
        acc.y += v0 * m0.y;
        acc.z += v0 * m0.z;
        acc.w += v0 * m0.w;
    }

    ((float4*)out)[(size_t)r * 16 + c] = acc;
}

// ---------------------------------------------------------------------------
// Launch
// ---------------------------------------------------------------------------
extern "C" void kernel_launch(void* const* d_in, const int* in_sizes, int n_in,
                              void* d_out, int out_size) {
    const float* x = (const float*)d_in[0];
    const int* adj_row = (const int*)d_in[1];
    const int* adj_col = (const int*)d_in[2];
    const float* adj_val = (const float*)d_in[3];
    const float* W = (const float*)d_in[4];
    const float* b = (const float*)d_in[5];
    float* out = (float*)d_out;

    const int n_nodes = in_sizes[0] / F_IN;
    const int n_edges = in_sizes[1];
    const int nscan = (n_nodes + SCAN_BLK - 1) / SCAN_BLK;

    // CSR build
    zero_count_kernel<<<(n_nodes + 255) / 256, 256>>>(n_nodes);
    hist_kernel<<<(n_edges + 255) / 256, 256>>>(adj_row, n_edges);
    scan_a_kernel<<<nscan, SCAN_BLK>>>(n_nodes);
    scan_b_kernel<<<1, SCAN_BLK>>>(nscan, n_nodes);
    scan_c_kernel<<<nscan, SCAN_BLK>>>(n_nodes);
    scatter_kernel<<<(n_edges + 255) / 256, 256>>>(adj_row, adj_col, adj_val,
                                                   n_edges);

    // GEMM
    gemm_kernel<<<(n_nodes + BM - 1) / BM, 256>>>(x, W, n_nodes);

    // Aggregate (bias folded in)
    {
        long long total = (long long)n_nodes * 16;
        int blocks = (int)((total + 255) / 256);
        agg_kernel<<<blocks, 256>>>(b, out, n_nodes);
    }
}

// round 6
// speedup vs baseline: 1.4104x; 1.1609x over previous
#include <cuda_runtime.h>
#include <cuda_bf16.h>
#include <cstdint>

#define MAX_NODES 100000
#define MAX_EDGES 1600000
#define F_IN      128
#define F_OUT     64

typedef unsigned long long ull;

// Scratch (allocation-free rule: __device__ globals)
__device__ __align__(16) float g_xw[(size_t)MAX_NODES * F_OUT];   // 25.6 MB
__device__ __align__(16) int2  g_edges[MAX_EDGES];                // {col, val-bits}
__device__ int g_count[MAX_NODES];
__device__ int g_offset[MAX_NODES + 1];
__device__ int g_pos[MAX_NODES];
__device__ int g_bsum[512];

#define SCAN_BLK 512

// ---------------------------------------------------------------------------
// Packed f32x2 helpers (SASS FFMA2 — ptxas never emits this from C++)
// ---------------------------------------------------------------------------
__device__ __forceinline__ ull f2_dup(float v) {
    ull r;
    asm("mov.b64 %0, {%1, %1};" : "=l"(r) : "f"(v));
    return r;
}
__device__ __forceinline__ ull fma_f32x2(ull a, ull b, ull c) {
    ull d;
    asm("fma.rn.f32x2 %0, %1, %2, %3;" : "=l"(d) : "l"(a), "l"(b), "l"(c));
    return d;
}
__device__ __forceinline__ void f2_unpack(ull v, float& lo, float& hi) {
    asm("mov.b64 {%0, %1}, %2;" : "=f"(lo), "=f"(hi) : "l"(v));
}

// ---------------------------------------------------------------------------
// CSR build: zero -> histogram -> scan_a -> scan_bc -> scatter
// ---------------------------------------------------------------------------
__global__ void zero_count_kernel(int n_nodes) {
    int i = blockIdx.x * blockDim.x + threadIdx.x;
    if (i < n_nodes) g_count[i] = 0;
}

__global__ void hist_kernel(const int* __restrict__ adj_row, int n_edges) {
    int e = blockIdx.x * blockDim.x + threadIdx.x;
    if (e < n_edges) {
        int r = adj_row[e];
        if ((unsigned)r < (unsigned)MAX_NODES) atomicAdd(&g_count[r], 1);
    }
}

__global__ __launch_bounds__(SCAN_BLK) void scan_a_kernel(int n_nodes) {
    __shared__ int s[SCAN_BLK];
    int t = threadIdx.x;
    int idx = blockIdx.x * SCAN_BLK + t;
    s[t] = (idx < n_nodes) ? g_count[idx] : 0;
    __syncthreads();
#pragma unroll
    for (int d = SCAN_BLK / 2; d > 0; d >>= 1) {
        if (t < d) s[t] += s[t + d];
        __syncthreads();
    }
    if (t == 0) g_bsum[blockIdx.x] = s[0];
}

// Fused: every block redundantly scans the block sums in smem (196 ints),
// then does its local scan and writes offsets — removes the single-block
// scan_b launch (~5us of dead time).
__global__ __launch_bounds__(SCAN_BLK) void scan_bc_kernel(int nblocks,
                                                           int n_nodes) {
    __shared__ int bs[SCAN_BLK];
    __shared__ int s[SCAN_BLK];
    int t = threadIdx.x;

    bs[t] = (t < nblocks) ? g_bsum[t] : 0;
    __syncthreads();
    for (int d = 1; d < SCAN_BLK; d <<= 1) {
        int tmp = (t >= d) ? bs[t - d] : 0;
        __syncthreads();
        bs[t] += tmp;
        __syncthreads();
    }
    int prefix = (blockIdx.x == 0) ? 0 : bs[blockIdx.x - 1];
    if (blockIdx.x == 0 && t == 0) g_offset[n_nodes] = bs[nblocks - 1];

    int idx = blockIdx.x * SCAN_BLK + t;
    int v = (idx < n_nodes) ? g_count[idx] : 0;
    s[t] = v;
    __syncthreads();
    for (int d = 1; d < SCAN_BLK; d <<= 1) {
        int tmp = (t >= d) ? s[t - d] : 0;
        __syncthreads();
        s[t] += tmp;
        __syncthreads();
    }
    if (idx < n_nodes) {
        int off = prefix + s[t] - v;  // exclusive
        g_offset[idx] = off;
        g_pos[idx] = off;
    }
}

__global__ void scatter_kernel(const int* __restrict__ adj_row,
                               const int* __restrict__ adj_col,
                               const float* __restrict__ adj_val,
                               int n_edges) {
    int e = blockIdx.x * blockDim.x + threadIdx.x;
    if (e >= n_edges) return;
    int r = adj_row[e];
    if ((unsigned)r >= (unsigned)MAX_NODES) return;
    int pos = atomicAdd(&g_pos[r], 1);
    if ((unsigned)pos < (unsigned)MAX_EDGES)
        g_edges[pos] = make_int2(adj_col[e], __float_as_int(adj_val[e]));
}

// ---------------------------------------------------------------------------
// Dense GEMM  xw[M,64] = x[M,128] @ W[128,64]
// BM=32, 128 threads, each thread: 4 rows x 4 cols via packed fma.f32x2.
// Per k-step: 2x LDS.64 (row pairs) + LDS.128 (4 w) + 4 dup-movs + 8 FFMA2.
// ---------------------------------------------------------------------------
#define BM 32

__global__ __launch_bounds__(128) void gemm_kernel(
    const float* __restrict__ x,
    const float* __restrict__ W,
    int n_nodes) {
    __shared__ __align__(16) float xsT[F_IN][BM];      // [k][row]  16 KB
    __shared__ __align__(16) float Ws[F_IN][F_OUT];    // [k][f]    32 KB

    const int t = threadIdx.x;           // 0..127
    const int row0 = blockIdx.x * BM;

    // Load W (2048 float4), coalesced
    {
        const float4* W4 = (const float4*)W;
        float4* Ws4 = (float4*)Ws;
#pragma unroll
        for (int i = 0; i < 16; i++) Ws4[t + i * 128] = W4[t + i * 128];
    }
    // Load x tile transposed: row = t&31, kc0 = t>>5 (0..3), 8 iters
    {
        const int row = t & 31;
        const int kc0 = t >> 5;
        const int grow = row0 + row;
        const bool ok = (grow < n_nodes);
        const float4* xrow4 =
            (const float4*)(x + (size_t)(ok ? grow : 0) * F_IN);
#pragma unroll
        for (int i = 0; i < 8; i++) {
            int kc = kc0 + i * 4;
            float4 v = ok ? xrow4[kc] : make_float4(0.f, 0.f, 0.f, 0.f);
            xsT[kc * 4 + 0][row] = v.x;
            xsT[kc * 4 + 1][row] = v.y;
            xsT[kc * 4 + 2][row] = v.z;
            xsT[kc * 4 + 3][row] = v.w;
        }
    }
    __syncthreads();

    const int tx = t & 15;   // col group: cols tx*4..+3
    const int ty = t >> 4;   // row group: rows ty*4..+3 (0..7)

    ull acc[2][4];  // [rowpair][col]; lo=row 2i, hi=row 2i+1 (within the 4)
#pragma unroll
    for (int i = 0; i < 2; i++)
#pragma unroll
        for (int j = 0; j < 4; j++) acc[i][j] = f2_dup(0.f);

#pragma unroll 8
    for (int k = 0; k < F_IN; k++) {
        ull xa = *(const ull*)&xsT[k][ty * 4];      // rows ty*4, ty*4+1
        ull xb = *(const ull*)&xsT[k][ty * 4 + 2];  // rows ty*4+2, ty*4+3
        float4 wv = *(const float4*)&Ws[k][tx * 4];
        ull w0 = f2_dup(wv.x);
        ull w1 = f2_dup(wv.y);
        ull w2 = f2_dup(wv.z);
        ull w3 = f2_dup(wv.w);
        acc[0][0] = fma_f32x2(xa, w0, acc[0][0]);
        acc[0][1] = fma_f32x2(xa, w1, acc[0][1]);
        acc[0][2] = fma_f32x2(xa, w2, acc[0][2]);
        acc[0][3] = fma_f32x2(xa, w3, acc[0][3]);
        acc[1][0] = fma_f32x2(xb, w0, acc[1][0]);
        acc[1][1] = fma_f32x2(xb, w1, acc[1][1]);
        acc[1][2] = fma_f32x2(xb, w2, acc[1][2]);
        acc[1][3] = fma_f32x2(xb, w3, acc[1][3]);
    }

    // Store 4 rows x 4 cols
#pragma unroll
    for (int i = 0; i < 2; i++) {
        float lo[4], hi[4];
#pragma unroll
        for (int j = 0; j < 4; j++) f2_unpack(acc[i][j], lo[j], hi[j]);
        int r_lo = row0 + ty * 4 + i * 2;
        int r_hi = r_lo + 1;
        if (r_lo < n_nodes) {
            float4 v = make_float4(lo[0], lo[1], lo[2], lo[3]);
            ((float4*)(g_xw + (size_t)r_lo * F_OUT))[tx] = v;
        }
        if (r_hi < n_nodes) {
            float4 v = make_float4(hi[0], hi[1], hi[2], hi[3]);
            ((float4*)(g_xw + (size_t)r_hi * F_OUT))[tx] = v;
        }
    }
}

// ---------------------------------------------------------------------------
// CSR aggregation: 16 threads per row, register accumulation, no atomics.
// ---------------------------------------------------------------------------
__global__ __launch_bounds__(256) void agg_kernel(
    const float* __restrict__ b,
    float* __restrict__ out,
    int n_nodes) {
    int gid = blockIdx.x * blockDim.x + threadIdx.x;
    int r = gid >> 4;
    if (r >= n_nodes) return;
    int c = gid & 15;  // float4 chunk

    int s = g_offset[r];
    int e = g_offset[r + 1];

    float4 acc = ((const float4*)b)[c];
    const float4* xw4 = (const float4*)g_xw;

    int i = s;
    for (; i + 1 < e; i += 2) {
        int2 e0 = g_edges[i];
        int2 e1 = g_edges[i + 1];
        float4 m0 = xw4[(size_t)e0.x * 16 + c];
        float4 m1 = xw4[(size_t)e1.x * 16 + c];
        float v0 = __int_as_float(e0.y);
        float v1 = __int_as_float(e1.y);
        acc.x += v0 * m0.x + v1 * m1.x;
        acc.y += v0 * m0.y + v1 * m1.y;
        acc.z += v0 * m0.z + v1 * m1.z;
        acc.w += v0 * m0.w + v1 * m1.w;
    }
    if (i < e) {
        int2 e0 = g_edges[i];
        float4 m0 = xw4[(size_t)e0.x * 16 + c];
        float v0 = __int_as_float(e0.y);
        acc.x += v0 * m0.x;
        acc.y += v0 * m0.y;
        acc.z += v0 * m0.z;
        acc.w += v0 * m0.w;
    }

    ((float4*)out)[(size_t)r * 16 + c] = acc;
}

// ---------------------------------------------------------------------------
// Launch
// ---------------------------------------------------------------------------
extern "C" void kernel_launch(void* const* d_in, const int* in_sizes, int n_in,
                              void* d_out, int out_size) {
    const float* x = (const float*)d_in[0];
    const int* adj_row = (const int*)d_in[1];
    const int* adj_col = (const int*)d_in[2];
    const float* adj_val = (const float*)d_in[3];
    const float* W = (const float*)d_in[4];
    const float* b = (const float*)d_in[5];
    float* out = (float*)d_out;

    const int n_nodes = in_sizes[0] / F_IN;
    const int n_edges = in_sizes[1];
    const int nscan = (n_nodes + SCAN_BLK - 1) / SCAN_BLK;

    // CSR build
    zero_count_kernel<<<(n_nodes + 255) / 256, 256>>>(n_nodes);
    hist_kernel<<<(n_edges + 255) / 256, 256>>>(adj_row, n_edges);
    scan_a_kernel<<<nscan, SCAN_BLK>>>(n_nodes);
    scan_bc_kernel<<<nscan, SCAN_BLK>>>(nscan, n_nodes);
    scatter_kernel<<<(n_edges + 255) / 256, 256>>>(adj_row, adj_col, adj_val,
                                                   n_edges);

    // GEMM (packed f32x2)
    gemm_kernel<<<(n_nodes + BM - 1) / BM, 128>>>(x, W, n_nodes);

    // Aggregate (bias folded in)
    {
        long long total = (long long)n_nodes * 16;
        int blocks = (int)((total + 255) / 256);
        agg_kernel<<<blocks, 256>>>(b, out, n_nodes);
    }
}